// round 10
// baseline (speedup 1.0000x reference)
#include <cuda_runtime.h>
#include <cuda_bf16.h>
#include <cstdint>

#define F_DIM   512
#define F4      (F_DIM / 4)     // 128 float4 per row
#define NGROUPS 1024
#define OUTK    7
#define TPB     128             // one float4 column per thread, 4 warps
#define RPB     85              // rows per block -> grid ~1177 (~7.95/SM, 1 wave)

// Scratch: zero-initialized .bss; the finalizing block re-zeros everything it
// consumed, so every launch (and graph replay) sees zeros on entry.
__device__ float    g_acc[NGROUPS][8];   // [7 dot-partials, count]
__device__ unsigned g_done;              // completed-block counter

// ---------------------------------------------------------------------------
// Single launch: perfectly balanced accumulate + last-block finalize.
// Block owns rows [bid*RPB, bid*RPB+RPB). Finds group runs in its slice
// (batch sorted -> contiguous, block-uniform), accumulates each run with an
// 8-deep streaming pipeline, dots with W, block-reduces, atomicAdds 7 floats
// + count into g_acc. The last block to finish divides by count, adds bias,
// writes out, and re-zeros the scratch.
// ---------------------------------------------------------------------------
__global__ __launch_bounds__(TPB, 8)
void accum_kernel(const float4* __restrict__ x4,
                  const int*    __restrict__ bw,   // batch as 32-bit words
                  const float4* __restrict__ W4g,
                  const float*  __restrict__ bias,
                  float*        __restrict__ out,
                  int N)
{
    const int t    = threadIdx.x;       // 0..127 == float4 column
    const int warp = t >> 5, lane = t & 31;
    const int r0   = blockIdx.x * RPB;
    const int nRows = min(RPB, N - r0);

    __shared__ int   sgid[RPB];
    __shared__ int   smi[4];
    __shared__ float redw[4][OUTK];
    __shared__ int   s_last;

    // dtype probe (batch sorted 0..1023, last element nonzero):
    // int64 storage => odd 32-bit words (high words) are zero. L2-hot.
    const bool is64 = (bw[N - 1] == 0) && (bw[N - 3] == 0) && (bw[N - 5] == 0);

    if (nRows > 0) {
        // load this slice's group ids
        if (t < nRows) {
            int g = is64 ? bw[2 * (r0 + t)] : bw[r0 + t];
            sgid[t] = min(max(g, 0), NGROUPS - 1);
        }
        __syncthreads();

        const int BIG = 0x7fffffff;
        int i = 0;
        while (i < nRows) {
            const int gid = sgid[i];

            // --- find run end j: min over threads of first mismatch > i
            int cand = (t < nRows && t > i && sgid[t] != gid) ? t : BIG;
            #pragma unroll
            for (int off = 16; off > 0; off >>= 1)
                cand = min(cand, __shfl_xor_sync(0xffffffff, cand, off));
            if (lane == 0) smi[warp] = cand;
            __syncthreads();
            const int j = min(min(min(smi[0], smi[1]), min(smi[2], smi[3])), nRows);
            __syncthreads();

            // --- accumulate rows [r0+i, r0+j), 8-deep streaming pipeline
            float4 a0 = make_float4(0.f, 0.f, 0.f, 0.f);
            float4 a1 = make_float4(0.f, 0.f, 0.f, 0.f);
            float4 a2 = make_float4(0.f, 0.f, 0.f, 0.f);
            float4 a3 = make_float4(0.f, 0.f, 0.f, 0.f);
            const float4* p = x4 + (size_t)(r0 + i) * F4 + t;
            int n = j - i;
            for (; n >= 8; n -= 8, p += 8 * F4) {
                float4 v0 = __ldcs(p + 0 * F4);
                float4 v1 = __ldcs(p + 1 * F4);
                float4 v2 = __ldcs(p + 2 * F4);
                float4 v3 = __ldcs(p + 3 * F4);
                float4 v4 = __ldcs(p + 4 * F4);
                float4 v5 = __ldcs(p + 5 * F4);
                float4 v6 = __ldcs(p + 6 * F4);
                float4 v7 = __ldcs(p + 7 * F4);
                a0.x += v0.x; a0.y += v0.y; a0.z += v0.z; a0.w += v0.w;
                a1.x += v1.x; a1.y += v1.y; a1.z += v1.z; a1.w += v1.w;
                a2.x += v2.x; a2.y += v2.y; a2.z += v2.z; a2.w += v2.w;
                a3.x += v3.x; a3.y += v3.y; a3.z += v3.z; a3.w += v3.w;
                a0.x += v4.x; a0.y += v4.y; a0.z += v4.z; a0.w += v4.w;
                a1.x += v5.x; a1.y += v5.y; a1.z += v5.z; a1.w += v5.w;
                a2.x += v6.x; a2.y += v6.y; a2.z += v6.z; a2.w += v6.w;
                a3.x += v7.x; a3.y += v7.y; a3.z += v7.z; a3.w += v7.w;
            }
            for (; n > 0; n--, p += F4) {
                float4 v = __ldcs(p);
                a0.x += v.x; a0.y += v.y; a0.z += v.z; a0.w += v.w;
            }
            a0.x += a1.x; a0.y += a1.y; a0.z += a1.z; a0.w += a1.w;
            a2.x += a3.x; a2.y += a3.y; a2.z += a3.z; a2.w += a3.w;
            a0.x += a2.x; a0.y += a2.y; a0.z += a2.z; a0.w += a2.w;

            // --- 7 partial dots against W (tiny, L2-resident)
            float pr[OUTK];
            #pragma unroll
            for (int k = 0; k < OUTK; k++) {
                float4 w = __ldg(&W4g[k * F4 + t]);
                pr[k] = a0.x * w.x + a0.y * w.y + a0.z * w.z + a0.w * w.w;
            }
            #pragma unroll
            for (int off = 16; off > 0; off >>= 1) {
                #pragma unroll
                for (int k = 0; k < OUTK; k++)
                    pr[k] += __shfl_xor_sync(0xffffffff, pr[k], off);
            }
            if (lane == 0) {
                #pragma unroll
                for (int k = 0; k < OUTK; k++) redw[warp][k] = pr[k];
            }
            __syncthreads();
            if (t < OUTK)
                atomicAdd(&g_acc[gid][t],
                          redw[0][t] + redw[1][t] + redw[2][t] + redw[3][t]);
            if (t == OUTK)
                atomicAdd(&g_acc[gid][7], (float)(j - i));
            __syncthreads();

            i = j;
        }
    }

    // --- last-block-done finalize (single launch, no second kernel)
    __threadfence();                       // order g_acc atomics before counter
    if (t == 0) {
        unsigned prev = atomicAdd(&g_done, 1u);
        s_last = (prev == gridDim.x - 1) ? 1 : 0;
    }
    __syncthreads();
    if (s_last) {
        __threadfence();                   // acquire: see all blocks' g_acc
        // 1024 groups / 128 threads = 8 groups per thread; L2-hot.
        #pragma unroll
        for (int q = 0; q < NGROUPS / TPB; q++) {
            const int g = q * TPB + t;
            float4 s0 = *(const float4*)&g_acc[g][0];
            float4 s1 = *(const float4*)&g_acc[g][4];
            float inv = 1.0f / fmaxf(s1.w, 1.0f);   // s1.w = count
            out[g * OUTK + 0] = s0.x * inv + bias[0];
            out[g * OUTK + 1] = s0.y * inv + bias[1];
            out[g * OUTK + 2] = s0.z * inv + bias[2];
            out[g * OUTK + 3] = s0.w * inv + bias[3];
            out[g * OUTK + 4] = s1.x * inv + bias[4];
            out[g * OUTK + 5] = s1.y * inv + bias[5];
            out[g * OUTK + 6] = s1.z * inv + bias[6];
            float4 z = make_float4(0.f, 0.f, 0.f, 0.f);
            *(float4*)&g_acc[g][0] = z;
            *(float4*)&g_acc[g][4] = z;
        }
        if (t == 0) g_done = 0;            // restore invariant for next replay
    }
}

// ---------------------------------------------------------------------------
// Inputs (metadata order):
//   d_in[0] = x          float32 [100000, 512]
//   d_in[1] = edge_index (unused)
//   d_in[2] = edge_attr  (unused)
//   d_in[3] = batch      int64-or-int32 [100000] (probed in-kernel)
//   d_in[4] = W          float32 [7, 512]
//   d_in[5] = b          float32 [7]
// Output: float32 [1024, 7]
// ---------------------------------------------------------------------------
extern "C" void kernel_launch(void* const* d_in, const int* in_sizes, int n_in,
                              void* d_out, int out_size)
{
    const float4* x4  = (const float4*)d_in[0];
    const int*    bw  = (const int*)d_in[3];
    const float4* W4g = (const float4*)d_in[4];
    const float*  b   = (const float*)d_in[5];
    float*        out = (float*)d_out;

    const int N = in_sizes[3];

    accum_kernel<<<(N + RPB - 1) / RPB, TPB>>>(x4, bw, W4g, b, out, N);
}

// round 11
// speedup vs baseline: 1.0115x; 1.0115x over previous
#include <cuda_runtime.h>
#include <cuda_bf16.h>
#include <cstdint>

#define F_DIM   512
#define F4      (F_DIM / 4)     // 128 float4 per row
#define NGROUPS 1024
#define OUTK    7
#define TPB     128             // one float4 column per thread, 4 warps
#define RPSTG   2               // rows per pipeline stage
#define NSTG    6               // smem ring stages (24 KB)
#define IDEPTH  (NSTG - 1)      // issue-ahead depth (5 stages = 10 rows)

// --- cp.async helpers -------------------------------------------------------
__device__ __forceinline__ void cp16(uint32_t dst_smem, const void* src, bool pred) {
    asm volatile(
        "{ .reg .pred p; setp.ne.b32 p, %2, 0;\n\t"
        "@p cp.async.cg.shared.global [%0], [%1], 16; }"
        :: "r"(dst_smem), "l"(src), "r"((int)pred) : "memory");
}
__device__ __forceinline__ void cp_commit() {
    asm volatile("cp.async.commit_group;" ::: "memory");
}
template <int K>
__device__ __forceinline__ void cp_wait() {
    asm volatile("cp.async.wait_group %0;" :: "n"(K) : "memory");
}

// ---------------------------------------------------------------------------
// Single fused kernel. Block g owns group g exclusively (batch is sorted):
//   [lo, hi) found by a fully parallel 3-round probe (unchanged from R8).
// Mainloop: cp.async smem ring, 6 stages x 2 rows, depth 5 — per-block 20 KB
// of guaranteed in-flight reads, no load registers, no mainloop syncs
// (thread t copies and consumes only its own 16B column slice).
// Epilogue: 7 dots vs W, warp+smem reduce, out = sum·Wᵀ/cnt + bias.
// ---------------------------------------------------------------------------
__global__ __launch_bounds__(TPB, 8)
void mognn_kernel(const float4* __restrict__ x4,
                  const int*    __restrict__ bw,   // batch as 32-bit words
                  const float4* __restrict__ W4g,
                  const float*  __restrict__ bias,
                  float*        __restrict__ out,
                  int N)
{
    const int g = blockIdx.x;
    const int t = threadIdx.x;          // 0..127 == float4 column
    const int warp = t >> 5, lane = t & 31;

    __shared__ float4 sbuf[NSTG][RPSTG][TPB];   // 24 KB ring
    __shared__ int    sm[4];
    __shared__ float  redw[4][OUTK];

    // --- dtype probe (batch sorted 0..1023, last element nonzero):
    // int64 storage => odd 32-bit words (high words) are zero. L2-hot.
    const bool is64 = (bw[N - 1] == 0) && (bw[N - 3] == 0) && (bw[N - 5] == 0);
    auto bval = [&](int i) -> int { return is64 ? bw[2 * i] : bw[i]; };

    const int BIG = NGROUPS + 1;
    const int team   = (t >= 64);       // warps 0,1 -> lo; warps 2,3 -> hi
    const int tt     = t & 63;
    const int target = team ? (g + 1) : g;

    int lo, hi;
    {
        // ---- round 1: shared probes @ stride1
        const int stride1 = (N + TPB - 1) / TPB;          // 782 for N=100000
        int idx = min(t * stride1, N - 1);
        int v = bval(idx);
        int c_lo = (v < g)     ? idx : -1;
        int c_hi = (v < g + 1) ? idx : -1;
        #pragma unroll
        for (int off = 16; off > 0; off >>= 1) {
            c_lo = max(c_lo, __shfl_xor_sync(0xffffffff, c_lo, off));
            c_hi = max(c_hi, __shfl_xor_sync(0xffffffff, c_hi, off));
        }
        if (lane == 0) { sm[warp] = c_lo; }
        __syncthreads();
        int a_lo = max(max(sm[0], sm[1]), max(sm[2], sm[3]));
        __syncthreads();
        if (lane == 0) { sm[warp] = c_hi; }
        __syncthreads();
        int a_hi = max(max(sm[0], sm[1]), max(sm[2], sm[3]));
        __syncthreads();

        // ---- round 2: two teams, stride2 probes
        const int stride2 = (stride1 + 63) / 64;          // 13
        int abase = team ? a_hi : a_lo;
        int pos = abase + 1 + tt * stride2;
        int v2 = (pos < N) ? bval(pos) : BIG;
        int c = (v2 < target) ? pos : -1;
        #pragma unroll
        for (int off = 16; off > 0; off >>= 1)
            c = max(c, __shfl_xor_sync(0xffffffff, c, off));
        if (lane == 0) sm[warp] = c;
        __syncthreads();
        int best_lo = max(a_lo, max(sm[0], sm[1]));
        int best_hi = max(a_hi, max(sm[2], sm[3]));
        __syncthreads();

        // ---- round 3: final <=stride2 positions, one parallel load
        abase = team ? best_hi : best_lo;
        pos = abase + 1 + tt;
        int v3 = (tt < stride2 && pos < N) ? bval(pos) : BIG;
        c = (v3 < target) ? pos : -1;
        #pragma unroll
        for (int off = 16; off > 0; off >>= 1)
            c = max(c, __shfl_xor_sync(0xffffffff, c, off));
        if (lane == 0) sm[warp] = c;
        __syncthreads();
        lo = max(best_lo, max(sm[0], sm[1])) + 1;
        hi = max(best_hi, max(sm[2], sm[3])) + 1;
    }
    const int cnt = hi - lo;
    const int nst = (cnt + RPSTG - 1) / RPSTG;   // total pipeline stages

    // --- cp.async ring mainloop (no syncs: thread t owns column t end-to-end)
    auto issue_stage = [&](int s) {
        const int slot = s % NSTG;
        const int base = lo + s * RPSTG;
        #pragma unroll
        for (int j = 0; j < RPSTG; j++) {
            const int row = base + j;
            uint32_t dst = (uint32_t)__cvta_generic_to_shared(&sbuf[slot][j][t]);
            cp16(dst, x4 + (size_t)row * F4 + t, row < hi);
        }
        cp_commit();
    };

    // prologue: exactly IDEPTH commits (real or empty)
    #pragma unroll
    for (int k = 0; k < IDEPTH; k++) {
        if (k < nst) issue_stage(k);
        else         cp_commit();
    }

    float4 a0 = make_float4(0.f, 0.f, 0.f, 0.f);
    float4 a1 = make_float4(0.f, 0.f, 0.f, 0.f);
    for (int s = 0; s < nst; s++) {
        cp_wait<IDEPTH - 1>();                    // oldest stage complete
        const int slot = s % NSTG;
        const int base = lo + s * RPSTG;
        float4 v0 = sbuf[slot][0][t];             // row base always valid
        a0.x += v0.x; a0.y += v0.y; a0.z += v0.z; a0.w += v0.w;
        if (base + 1 < hi) {
            float4 v1 = sbuf[slot][1][t];
            a1.x += v1.x; a1.y += v1.y; a1.z += v1.z; a1.w += v1.w;
        }
        const int nx = s + IDEPTH;
        if (nx < nst) issue_stage(nx);
        else          cp_commit();                // keep group count constant
    }
    cp_wait<0>();                                 // drain before smem reuse/exit
    a0.x += a1.x; a0.y += a1.y; a0.z += a1.z; a0.w += a1.w;

    // --- 7 partial dots against W (tiny, L2-resident)
    float pr[OUTK];
    #pragma unroll
    for (int k = 0; k < OUTK; k++) {
        float4 w = __ldg(&W4g[k * F4 + t]);
        pr[k] = a0.x * w.x + a0.y * w.y + a0.z * w.z + a0.w * w.w;
    }

    // --- reduce across 4 warps
    #pragma unroll
    for (int off = 16; off > 0; off >>= 1) {
        #pragma unroll
        for (int k = 0; k < OUTK; k++)
            pr[k] += __shfl_xor_sync(0xffffffff, pr[k], off);
    }
    if (lane == 0) {
        #pragma unroll
        for (int k = 0; k < OUTK; k++) redw[warp][k] = pr[k];
    }
    __syncthreads();

    if (t < OUTK) {
        float v = redw[0][t] + redw[1][t] + redw[2][t] + redw[3][t];
        out[g * OUTK + t] = v / fmaxf((float)cnt, 1.0f) + bias[t];
    }
}

// ---------------------------------------------------------------------------
// Inputs (metadata order):
//   d_in[0] = x          float32 [100000, 512]
//   d_in[1] = edge_index (unused)
//   d_in[2] = edge_attr  (unused)
//   d_in[3] = batch      int64-or-int32 [100000] (probed in-kernel)
//   d_in[4] = W          float32 [7, 512]
//   d_in[5] = b          float32 [7]
// Output: float32 [1024, 7]
// ---------------------------------------------------------------------------
extern "C" void kernel_launch(void* const* d_in, const int* in_sizes, int n_in,
                              void* d_out, int out_size)
{
    const float4* x4  = (const float4*)d_in[0];
    const int*    bw  = (const int*)d_in[3];
    const float4* W4g = (const float4*)d_in[4];
    const float*  b   = (const float*)d_in[5];
    float*        out = (float*)d_out;

    const int N = in_sizes[3];

    mognn_kernel<<<NGROUPS, TPB>>>(x4, bw, W4g, b, out, N);
}